// round 2
// baseline (speedup 1.0000x reference)
#include <cuda_runtime.h>
#include <math.h>

#define Bc  64
#define Sc  512
#define Tc  256
#define Ec  512
#define Hc  512
#define KQc 256
#define Vc  1000
#define BH  (Bc*Hc)
#define NBLK 128
#define NTHR 256

// ---------------- device scratch (no runtime allocation allowed) ----------------
__device__ float g_k[Bc*Sc*KQc];        // K cache [B,S,KQ]
__device__ float g_v[Bc*Sc*Ec];         // V cache [B,S,E]
__device__ float g_emb1[Vc*4*Hc];       // per-token LSTM1 input-side gate preact (+b_ih1+b_hh1)
__device__ float g_h1[2*BH];
__device__ float g_c1[2*BH];
__device__ float g_h2[2*BH];
__device__ float g_c2[2*BH];
__device__ float g_ctx[Bc*Ec];
__device__ float g_hid[Bc*Hc];
__device__ float g_attn_dummy[Bc*Sc];

// ---------------- software grid barrier ----------------
__device__ volatile unsigned g_bar_gen;
__device__ unsigned g_bar_cnt;

__device__ __forceinline__ void gsync() {
    __syncthreads();
    if (threadIdx.x == 0) {
        unsigned gen = g_bar_gen;
        __threadfence();
        if (atomicAdd(&g_bar_cnt, 1u) == NBLK - 1) {
            g_bar_cnt = 0u;
            __threadfence();
            g_bar_gen = gen + 1u;
        } else {
            while (g_bar_gen == gen) { }
        }
        __threadfence();
    }
    __syncthreads();
}

// ---------------- shared memory union ----------------
struct __align__(16) Smem {
    union {
        struct { float As[16][68]; float Ws[16][68]; } gm;      // 8.7 KB
        struct { float x[64][68]; float h[64][68]; } lstm;      // 34.8 KB
        struct { float qh[512]; float qs[256]; float sc[512];
                 float red[8]; float red2[8]; } attn;           // 5.2 KB
        struct { float a[64][68]; } hid;                        // 17.4 KB
    } u;
};

__device__ __forceinline__ float dot4(float4 a, float4 w) {
    return a.x*w.x + a.y*w.y + a.z*w.z + a.w*w.w;
}

// ---------------- 64x64 GEMM tile: C = A[M,K] @ W[N,K]^T + b1 (+b2) ----------------
__device__ void gemm_tile(const float* __restrict__ A, const float* __restrict__ W,
                          const float* __restrict__ b1, const float* __restrict__ b2,
                          float* __restrict__ C, int M, int N, int K, int m0, int n0,
                          Smem* s)
{
    int tid = threadIdx.x;
    int tx = tid & 15, ty = tid >> 4;
    float acc[4][4] = {};
    for (int kb = 0; kb < K; kb += 16) {
        #pragma unroll
        for (int i = tid; i < 1024; i += NTHR) {
            int r = i >> 4, kk = i & 15;
            int ra = m0 + r; if (ra >= M) ra = M - 1;
            s->u.gm.As[kk][r] = A[(size_t)ra * K + kb + kk];
            s->u.gm.Ws[kk][r] = W[(size_t)(n0 + r) * K + kb + kk];
        }
        __syncthreads();
        #pragma unroll
        for (int kk = 0; kk < 16; kk++) {
            float4 a4 = *(const float4*)&s->u.gm.As[kk][ty * 4];
            float4 w4 = *(const float4*)&s->u.gm.Ws[kk][tx * 4];
            float ar[4] = {a4.x, a4.y, a4.z, a4.w};
            float wr[4] = {w4.x, w4.y, w4.z, w4.w};
            #pragma unroll
            for (int i = 0; i < 4; i++)
                #pragma unroll
                for (int j = 0; j < 4; j++)
                    acc[i][j] += ar[i] * wr[j];
        }
        __syncthreads();
    }
    #pragma unroll
    for (int i = 0; i < 4; i++) {
        int row = m0 + ty * 4 + i;
        if (row < M) {
            #pragma unroll
            for (int j = 0; j < 4; j++) {
                int col = n0 + tx * 4 + j;
                float v = acc[i][j] + b1[col];
                if (b2) v += b2[col];
                C[(size_t)row * N + col] = v;
            }
        }
    }
    __syncthreads();
}

// ---------------- LSTM phase (one step, one layer) ----------------
// block = j-tile of 4; thread = (b, jl). HASX: layer2 (x = h1_nxt); else layer1 (x from table)
template<bool HASX>
__device__ void lstm_phase(const float* __restrict__ hin, const float* __restrict__ cin,
                           float* __restrict__ hout, float* __restrict__ cout,
                           const float* __restrict__ xsrc,
                           const int* __restrict__ y, int t,
                           const float* __restrict__ Wih, const float* __restrict__ Whh,
                           const float* __restrict__ bih, const float* __restrict__ bhh,
                           Smem* s)
{
    int tid = threadIdx.x;
    int b = tid & 63, jl = tid >> 6;
    int j = blockIdx.x * 4 + jl;

    float ai, af, ag, ao;
    if (!HASX) {
        int tok = (t == 0) ? 0 : y[b * Tc + t - 1];
        const float* e = g_emb1 + (size_t)tok * (4 * Hc);
        ai = e[j]; af = e[512 + j]; ag = e[1024 + j]; ao = e[1536 + j];
    } else {
        ai = bih[j] + bhh[j];
        af = bih[512 + j] + bhh[512 + j];
        ag = bih[1024 + j] + bhh[1024 + j];
        ao = bih[1536 + j] + bhh[1536 + j];
    }

    const float* wh0 = Whh + (size_t)j * Hc;
    const float* wh1 = Whh + (size_t)(512 + j) * Hc;
    const float* wh2 = Whh + (size_t)(1024 + j) * Hc;
    const float* wh3 = Whh + (size_t)(1536 + j) * Hc;
    const float* wi0 = HASX ? Wih + (size_t)j * Hc : nullptr;
    const float* wi1 = HASX ? Wih + (size_t)(512 + j) * Hc : nullptr;
    const float* wi2 = HASX ? Wih + (size_t)(1024 + j) * Hc : nullptr;
    const float* wi3 = HASX ? Wih + (size_t)(1536 + j) * Hc : nullptr;

    for (int kb = 0; kb < Hc; kb += 64) {
        #pragma unroll
        for (int i = tid; i < 4096; i += NTHR) {
            int bb = i >> 6, kk = i & 63;
            s->u.lstm.h[bb][kk] = hin[bb * Hc + kb + kk];
            if (HASX) s->u.lstm.x[bb][kk] = xsrc[bb * Hc + kb + kk];
        }
        __syncthreads();
        #pragma unroll
        for (int kk = 0; kk < 64; kk += 4) {
            float4 hv = *(const float4*)&s->u.lstm.h[b][kk];
            ai += dot4(hv, *(const float4*)(wh0 + kb + kk));
            af += dot4(hv, *(const float4*)(wh1 + kb + kk));
            ag += dot4(hv, *(const float4*)(wh2 + kb + kk));
            ao += dot4(hv, *(const float4*)(wh3 + kb + kk));
            if (HASX) {
                float4 xv = *(const float4*)&s->u.lstm.x[b][kk];
                ai += dot4(xv, *(const float4*)(wi0 + kb + kk));
                af += dot4(xv, *(const float4*)(wi1 + kb + kk));
                ag += dot4(xv, *(const float4*)(wi2 + kb + kk));
                ao += dot4(xv, *(const float4*)(wi3 + kb + kk));
            }
        }
        __syncthreads();
    }

    float si = 1.f / (1.f + __expf(-ai));
    float sf = 1.f / (1.f + __expf(-af));
    float so = 1.f / (1.f + __expf(-ao));
    float cN = sf * cin[b * Hc + j] + si * tanhf(ag);
    float hN = so * tanhf(cN);
    hout[b * Hc + j] = hN;
    cout[b * Hc + j] = cN;
}

// ---------------- q + attention phase (one block per b; blocks >= 64 skip) ----------------
__device__ void qattn_phase(int b, const float* __restrict__ h2n,
                            const float* __restrict__ Wq, const float* __restrict__ bq,
                            float* __restrict__ attn_out, Smem* s)
{
    int tid = threadIdx.x, warp = tid >> 5, lane = tid & 31;

    s->u.attn.qh[tid]       = h2n[b * Hc + tid];
    s->u.attn.qh[256 + tid] = h2n[b * Hc + 256 + tid];
    __syncthreads();

    // q[j] = h2[b] . Wq[j] + bq[j]
    for (int jj = warp; jj < KQc; jj += 8) {
        const float* wr = Wq + (size_t)jj * Hc;
        float sum = 0.f;
        #pragma unroll
        for (int u = 0; u < 16; u++) sum += s->u.attn.qh[lane + 32 * u] * wr[lane + 32 * u];
        #pragma unroll
        for (int o = 16; o; o >>= 1) sum += __shfl_down_sync(~0u, sum, o);
        if (lane == 0) s->u.attn.qs[jj] = sum + bq[jj];
    }
    __syncthreads();

    // scores
    for (int ss = warp; ss < Sc; ss += 8) {
        const float* kr = g_k + ((size_t)b * Sc + ss) * KQc;
        float sum = 0.f;
        #pragma unroll
        for (int u = 0; u < 8; u++) sum += s->u.attn.qs[lane + 32 * u] * kr[lane + 32 * u];
        #pragma unroll
        for (int o = 16; o; o >>= 1) sum += __shfl_down_sync(~0u, sum, o);
        if (lane == 0) s->u.attn.sc[ss] = sum * 0.0625f;  // 1/sqrt(256)
    }
    __syncthreads();

    // softmax over 512 (each thread holds 2)
    float v0 = s->u.attn.sc[tid], v1 = s->u.attn.sc[tid + 256];
    float m = fmaxf(v0, v1);
    #pragma unroll
    for (int o = 16; o; o >>= 1) m = fmaxf(m, __shfl_xor_sync(~0u, m, o));
    if (lane == 0) s->u.attn.red[warp] = m;
    __syncthreads();
    float mm = s->u.attn.red[0];
    #pragma unroll
    for (int w = 1; w < 8; w++) mm = fmaxf(mm, s->u.attn.red[w]);
    float e0 = __expf(v0 - mm), e1 = __expf(v1 - mm);
    float ssum = e0 + e1;
    #pragma unroll
    for (int o = 16; o; o >>= 1) ssum += __shfl_xor_sync(~0u, ssum, o);
    if (lane == 0) s->u.attn.red2[warp] = ssum;
    __syncthreads();
    float Z = 0.f;
    #pragma unroll
    for (int w = 0; w < 8; w++) Z += s->u.attn.red2[w];
    float inv = 1.f / Z;
    float p0 = e0 * inv, p1 = e1 * inv;
    s->u.attn.sc[tid] = p0;
    s->u.attn.sc[tid + 256] = p1;
    attn_out[tid] = p0;
    attn_out[tid + 256] = p1;
    __syncthreads();

    // ctx[b, e] = sum_s p[s] * V[b,s,e]; thread covers e pair
    int e = tid * 2;
    const float* vb = g_v + (size_t)b * Sc * Ec + e;
    float ax = 0.f, ay = 0.f;
    #pragma unroll 8
    for (int ss = 0; ss < Sc; ss++) {
        float p = s->u.attn.sc[ss];
        float2 vv = *(const float2*)(vb + (size_t)ss * Ec);
        ax += p * vv.x; ay += p * vv.y;
    }
    g_ctx[b * Ec + e]     = ax;
    g_ctx[b * Ec + e + 1] = ay;
}

// ---------------- hid = relu([h2|ctx] @ W1^T + b1) ----------------
__device__ void hid_phase(const float* __restrict__ h2n,
                          const float* __restrict__ W1, const float* __restrict__ b1, Smem* s)
{
    int tid = threadIdx.x;
    int b = tid & 63, jl = tid >> 6;
    int j = blockIdx.x * 4 + jl;
    const float* wr = W1 + (size_t)j * (Hc + Ec);
    float acc = b1[j];
    for (int kb = 0; kb < Hc + Ec; kb += 64) {
        #pragma unroll
        for (int i = tid; i < 4096; i += NTHR) {
            int bb = i >> 6, kk = i & 63, kg = kb + kk;
            s->u.hid.a[bb][kk] = (kg < Hc) ? h2n[bb * Hc + kg] : g_ctx[bb * Ec + kg - Hc];
        }
        __syncthreads();
        #pragma unroll
        for (int kk = 0; kk < 64; kk += 4) {
            float4 a4 = *(const float4*)&s->u.hid.a[b][kk];
            acc += dot4(a4, *(const float4*)(wr + kb + kk));
        }
        __syncthreads();
    }
    g_hid[b * Hc + j] = fmaxf(acc, 0.f);
}

// ---------------- logits = hid @ W_emb^T + b_cls ----------------
__device__ void logits_phase(const float* __restrict__ Wemb, const float* __restrict__ bcls,
                             float* __restrict__ outL, int t, Smem* s)
{
    int tid = threadIdx.x;
    int b = tid & 63, jl = tid >> 6;
    for (int tile = blockIdx.x; tile < Vc / 4; tile += NBLK) {   // 250 tiles
        int j = tile * 4 + jl;
        const float* wr = Wemb + (size_t)j * Hc;
        float acc = bcls[j];
        for (int kb = 0; kb < Hc; kb += 64) {
            #pragma unroll
            for (int i = tid; i < 4096; i += NTHR) {
                int bb = i >> 6, kk = i & 63;
                s->u.hid.a[bb][kk] = g_hid[bb * Hc + kb + kk];
            }
            __syncthreads();
            #pragma unroll
            for (int kk = 0; kk < 64; kk += 4) {
                float4 a4 = *(const float4*)&s->u.hid.a[b][kk];
                acc += dot4(a4, *(const float4*)(wr + kb + kk));
            }
            __syncthreads();
        }
        outL[((size_t)b * Tc + t) * Vc + j] = acc;
    }
}

// ---------------- persistent kernel ----------------
__global__ void __launch_bounds__(NTHR, 1)
decoder_kernel(const float* __restrict__ enc, const int* __restrict__ y,
               const float* __restrict__ Wemb,
               const float* __restrict__ Wih1, const float* __restrict__ bih1,
               const float* __restrict__ Whh1, const float* __restrict__ bhh1,
               const float* __restrict__ Wih2, const float* __restrict__ bih2,
               const float* __restrict__ Whh2, const float* __restrict__ bhh2,
               const float* __restrict__ Wq,  const float* __restrict__ bq,
               const float* __restrict__ Wk,  const float* __restrict__ bk,
               const float* __restrict__ Wv,  const float* __restrict__ bv,
               const float* __restrict__ W1,  const float* __restrict__ b1,
               const float* __restrict__ bcls,
               float* __restrict__ outL, float* __restrict__ attnB,
               int attnBS, int attnTS)
{
    __shared__ Smem s;
    int tid = threadIdx.x;

    // zero initial state (parity-0 buffers)
    for (int i = blockIdx.x * NTHR + tid; i < BH; i += NBLK * NTHR) {
        g_h1[i] = 0.f; g_c1[i] = 0.f; g_h2[i] = 0.f; g_c2[i] = 0.f;
    }
    gsync();

    // precompute: K cache, V cache, per-token LSTM1 input-side table
    {
        const int nKt = (Bc * Sc / 64) * (KQc / 64);   // 2048
        const int nVt = (Bc * Sc / 64) * (Ec / 64);    // 4096
        const int nEt = 16 * (4 * Hc / 64);            // 512 (M=1000 -> 16 row tiles)
        for (int idx = blockIdx.x; idx < nKt + nVt + nEt; idx += NBLK) {
            if (idx < nKt) {
                int m0 = (idx / (KQc / 64)) * 64, n0 = (idx % (KQc / 64)) * 64;
                gemm_tile(enc, Wk, bk, nullptr, g_k, Bc * Sc, KQc, Ec, m0, n0, &s);
            } else if (idx < nKt + nVt) {
                int i2 = idx - nKt;
                int m0 = (i2 / (Ec / 64)) * 64, n0 = (i2 % (Ec / 64)) * 64;
                gemm_tile(enc, Wv, bv, nullptr, g_v, Bc * Sc, Ec, Ec, m0, n0, &s);
            } else {
                int i2 = idx - nKt - nVt;
                int m0 = (i2 / 32) * 64, n0 = (i2 % 32) * 64;
                gemm_tile(Wemb, Wih1, bih1, bhh1, g_emb1, Vc, 4 * Hc, Hc, m0, n0, &s);
            }
        }
    }
    gsync();

    for (int t = 0; t < Tc; t++) {
        int cur = t & 1, nxt = cur ^ 1;

        lstm_phase<false>(g_h1 + cur * BH, g_c1 + cur * BH,
                          g_h1 + nxt * BH, g_c1 + nxt * BH,
                          nullptr, y, t, nullptr, Whh1, nullptr, nullptr, &s);
        gsync();

        lstm_phase<true>(g_h2 + cur * BH, g_c2 + cur * BH,
                         g_h2 + nxt * BH, g_c2 + nxt * BH,
                         g_h1 + nxt * BH, y, t, Wih2, Whh2, bih2, bhh2, &s);
        gsync();

        if (blockIdx.x < Bc)
            qattn_phase(blockIdx.x, g_h2 + nxt * BH, Wq, bq,
                        attnB + (size_t)blockIdx.x * attnBS + (size_t)t * attnTS, &s);
        gsync();

        hid_phase(g_h2 + nxt * BH, W1, b1, &s);
        gsync();

        logits_phase(Wemb, bcls, outL, t, &s);
        // no barrier needed: next step's LSTM1 touches only h1/c1/table (disjoint from logits)
    }
}

// ---------------- launch ----------------
extern "C" void kernel_launch(void* const* d_in, const int* in_sizes, int n_in,
                              void* d_out, int out_size) {
    const float* enc   = (const float*)d_in[0];
    const int*   y     = (const int*)  d_in[1];
    const float* Wemb  = (const float*)d_in[2];
    const float* Wih1  = (const float*)d_in[3];
    const float* bih1  = (const float*)d_in[4];
    const float* Whh1  = (const float*)d_in[5];
    const float* bhh1  = (const float*)d_in[6];
    const float* Wih2  = (const float*)d_in[7];
    const float* bih2  = (const float*)d_in[8];
    const float* Whh2  = (const float*)d_in[9];
    const float* bhh2  = (const float*)d_in[10];
    const float* Wq    = (const float*)d_in[11];
    const float* bq    = (const float*)d_in[12];
    const float* Wk    = (const float*)d_in[13];
    const float* bk    = (const float*)d_in[14];
    const float* Wv    = (const float*)d_in[15];
    const float* bv    = (const float*)d_in[16];
    const float* W1    = (const float*)d_in[17];
    const float* b1    = (const float*)d_in[18];
    const float* bcls  = (const float*)d_in[19];

    float* outL = (float*)d_out;
    long long need = (long long)Bc * Tc * Vc + (long long)Bc * Tc * Sc;

    float* attnB; int attnBS, attnTS;
    if ((long long)out_size >= need) {
        attnB = outL + (size_t)Bc * Tc * Vc;
        attnBS = Tc * Sc; attnTS = Sc;
    } else {
        cudaGetSymbolAddress((void**)&attnB, g_attn_dummy);
        attnBS = Sc; attnTS = 0;
    }

    decoder_kernel<<<NBLK, NTHR>>>(enc, y, Wemb, Wih1, bih1, Whh1, bhh1,
                                   Wih2, bih2, Whh2, bhh2, Wq, bq, Wk, bk,
                                   Wv, bv, W1, b1, bcls, outL, attnB, attnBS, attnTS);
}